// round 16
// baseline (speedup 1.0000x reference)
#include <cuda_runtime.h>
#include <cstdint>

// Problem constants
#define HID   512
#define NSTEP 8192          // BS*T = 1024*8
#define G4H   2048          // 4*HID
#define DIN   512

// Scan config: 64 CTAs; each owns 8 fwd units AND 8 bwd units, alternating
// phases so each direction's publish propagates during the other's compute.
#define NCS          64
#define SCAN_THREADS 512
#define HC           8

// GEMM config
#define BM 128
#define BN 128
#define BK 16

__device__ float g_gates[(size_t)2 * NSTEP * G4H];
// Published hidden state (R11 packed layout): [dir][parity][e]
__device__ __align__(128) unsigned long long g_hbuf[2][2][HID];

// ---------------------------------------------------------------------------
__device__ __forceinline__ void st_rel(unsigned long long* p, unsigned long long v) {
    asm volatile("st.global.relaxed.gpu.u64 [%0], %1;" :: "l"(p), "l"(v) : "memory");
}
__device__ __forceinline__ void ld_rel_v2(const unsigned long long* p,
                                          unsigned long long& a, unsigned long long& b) {
    asm volatile("ld.relaxed.gpu.global.v2.u64 {%0, %1}, [%2];"
                 : "=l"(a), "=l"(b) : "l"(p) : "memory");
}
// Hardware tanh (MUFU.TANH): one op per transcendental.
__device__ __forceinline__ float htanh(float x) {
    float y;
    asm("tanh.approx.f32 %0, %1;" : "=f"(y) : "f"(x));
    return y;
}
__device__ __forceinline__ float hsigmoid(float x) {
    return fmaf(htanh(0.5f * x), 0.5f, 0.5f);
}

// ---------------------------------------------------------------------------
// Kernel 1: gates GEMM with register-staged double buffering (R15).
// ---------------------------------------------------------------------------
__global__ __launch_bounds__(256) void gates_gemm(
    const float* __restrict__ x,
    const float* __restrict__ Wif, const float* __restrict__ bf,
    const float* __restrict__ Wib, const float* __restrict__ bb)
{
    const int dir = blockIdx.z;
    const float* __restrict__ W    = dir ? Wib : Wif;
    const float* __restrict__ bias = dir ? bb  : bf;
    float* __restrict__ out = g_gates + (size_t)dir * NSTEP * G4H;

    __shared__ __align__(16) float As[BK][BM + 4];
    __shared__ __align__(16) float Bs[BK][BN + 4];

    const int tid  = threadIdx.x;
    const int row0 = blockIdx.y * BM;
    const int col0 = blockIdx.x * BN;
    const int tx = tid & 15;
    const int ty = tid >> 4;

    const int m0 = tid >> 2,         kq0 = (tid & 3) * 4;
    const int m1 = (tid + 256) >> 2, kq1 = ((tid + 256) & 3) * 4;
    const int xr0 = dir ? ((row0 + m0) ^ 7) : (row0 + m0);
    const int xr1 = dir ? ((row0 + m1) ^ 7) : (row0 + m1);
    const float* xp0 = x + (size_t)xr0 * DIN + kq0;
    const float* xp1 = x + (size_t)xr1 * DIN + kq1;
    const float* wp0 = W + (size_t)(col0 + m0) * DIN + kq0;
    const float* wp1 = W + (size_t)(col0 + m1) * DIN + kq1;

    float acc[8][8];
    #pragma unroll
    for (int i = 0; i < 8; i++)
        #pragma unroll
        for (int j = 0; j < 8; j++) acc[i][j] = 0.f;

    float4 xv0 = *(const float4*)(xp0);
    float4 xv1 = *(const float4*)(xp1);
    float4 wv0 = *(const float4*)(wp0);
    float4 wv1 = *(const float4*)(wp1);

    for (int k0 = 0; k0 < DIN; k0 += BK) {
        As[kq0 + 0][m0] = xv0.x; As[kq0 + 1][m0] = xv0.y;
        As[kq0 + 2][m0] = xv0.z; As[kq0 + 3][m0] = xv0.w;
        As[kq1 + 0][m1] = xv1.x; As[kq1 + 1][m1] = xv1.y;
        As[kq1 + 2][m1] = xv1.z; As[kq1 + 3][m1] = xv1.w;
        Bs[kq0 + 0][m0] = wv0.x; Bs[kq0 + 1][m0] = wv0.y;
        Bs[kq0 + 2][m0] = wv0.z; Bs[kq0 + 3][m0] = wv0.w;
        Bs[kq1 + 0][m1] = wv1.x; Bs[kq1 + 1][m1] = wv1.y;
        Bs[kq1 + 2][m1] = wv1.z; Bs[kq1 + 3][m1] = wv1.w;
        __syncthreads();

        if (k0 + BK < DIN) {
            xv0 = *(const float4*)(xp0 + k0 + BK);
            xv1 = *(const float4*)(xp1 + k0 + BK);
            wv0 = *(const float4*)(wp0 + k0 + BK);
            wv1 = *(const float4*)(wp1 + k0 + BK);
        }

        #pragma unroll
        for (int kk = 0; kk < BK; kk++) {
            float a[8], b[8];
            float4 a0 = *(const float4*)&As[kk][ty * 8];
            float4 a1 = *(const float4*)&As[kk][ty * 8 + 4];
            a[0]=a0.x; a[1]=a0.y; a[2]=a0.z; a[3]=a0.w;
            a[4]=a1.x; a[5]=a1.y; a[6]=a1.z; a[7]=a1.w;
            float4 b0 = *(const float4*)&Bs[kk][tx * 8];
            float4 b1 = *(const float4*)&Bs[kk][tx * 8 + 4];
            b[0]=b0.x; b[1]=b0.y; b[2]=b0.z; b[3]=b0.w;
            b[4]=b1.x; b[5]=b1.y; b[6]=b1.z; b[7]=b1.w;
            #pragma unroll
            for (int i = 0; i < 8; i++)
                #pragma unroll
                for (int j = 0; j < 8; j++)
                    acc[i][j] = fmaf(a[i], b[j], acc[i][j]);
        }
        __syncthreads();
    }

    #pragma unroll
    for (int i = 0; i < 8; i++) {
        size_t srow = row0 + ty * 8 + i;
        #pragma unroll
        for (int j = 0; j < 8; j++) {
            int c = col0 + tx * 8 + j;
            out[srow * G4H + c] = acc[i][j] + bias[c];
        }
    }
}

// ---------------------------------------------------------------------------
// Kernel 2: phase-interleaved bidirectional scan. 64 CTAs x 512 threads.
// Each CTA owns h'[ebase..ebase+8) of BOTH directions; per step it runs
// phase A (fwd) then phase B (bwd), hiding each direction's publish
// propagation behind the other's compute. Per-phase internals == R11.
// ---------------------------------------------------------------------------
__global__ void __launch_bounds__(SCAN_THREADS, 1) lstm_scan(
    const float* __restrict__ h0,
    const float* __restrict__ c0,
    const float* __restrict__ Whf,
    const float* __restrict__ Whb,
    float* __restrict__ out)
{
    const int cta   = blockIdx.x;        // 0..63
    const int tid   = threadIdx.x;
    const int ebase = cta * HC;

    __shared__ __align__(16) float sh[HID];        // polled hidden state (per phase)
    __shared__ __align__(16) float part[32][64];   // [gate*8 + h'][slice]
    __shared__ float zbuf[32];

    // ---- matvec role (shared by both phases): gate, h'-half, h-slice ----
    const int og = (tid >> 6) & 3;
    const int hh = tid >> 8;
    const int hs = tid & 63;

    float wF[4][8], wB[4][8];
    #pragma unroll
    for (int q = 0; q < 4; q++) {
        size_t row = (size_t)og * HID + ebase + hh * 4 + q;
        #pragma unroll
        for (int k = 0; k < 8; k++) {
            wF[q][k] = Whf[row * HID + hs * 8 + k];
            wB[q][k] = Whb[row * HID + hs * 8 + k];
        }
    }

    // ---- reduce role ----
    const int row = tid >> 4;            // 0..31 = gate*8 + h'
    const int sub = tid & 15;
    const int rg  = row >> 3;
    const int rh  = row & 7;
    const size_t gqF = (size_t)rg * HID + ebase + rh;                     // dir 0
    const size_t gqB = (size_t)NSTEP * G4H + (size_t)rg * HID + ebase + rh; // dir 1
    float gcurF = 0.f, gcurB = 0.f;
    if (sub == 0) {
        gcurF = __ldg(g_gates + gqF);
        gcurB = __ldg(g_gates + gqB);
    }

    // ---- update role (tid<8): owns h' = tid for both directions ----
    float cstF = 0.f, hvF = 0.f, cstB = 0.f, hvB = 0.f;
    if (tid < 8) {
        int e = ebase + tid;
        hvF = h0[e];           cstF = c0[e];
        hvB = h0[HID + e];     cstB = c0[HID + e];
        unsigned long long tag1 = 1ull << 32;
        st_rel(&g_hbuf[0][0][e], tag1 | (unsigned long long)__float_as_uint(hvF));
        st_rel(&g_hbuf[1][0][e], tag1 | (unsigned long long)__float_as_uint(hvB));
    }

    for (int s = 0; s < NSTEP; s++) {
        const int p = s & 1;
        const unsigned want = (unsigned)(s + 1);
        const unsigned long long ptag =
            ((unsigned long long)(unsigned)(s + 2)) << 32;

        #pragma unroll
        for (int ph = 0; ph < 2; ph++) {   // ph 0 = fwd, ph 1 = bwd
            // Phase 1: threads 0..255 poll 2 slots with one LDG.128
            if (tid < 256) {
                const unsigned long long* bp = &g_hbuf[ph][p][tid * 2];
                unsigned long long v0, v1;
                do {
                    ld_rel_v2(bp, v0, v1);
                } while ((unsigned)(v0 >> 32) != want || (unsigned)(v1 >> 32) != want);
                float2 hvals = make_float2(__uint_as_float((unsigned)v0),
                                           __uint_as_float((unsigned)v1));
                *(float2*)&sh[tid * 2] = hvals;
            }
            __syncthreads();   // S1

            // Phase 2: register-tiled matvec partials
            {
                float4 ha = *(const float4*)&sh[hs * 8];
                float4 hb = *(const float4*)&sh[hs * 8 + 4];
                float hr[8] = {ha.x, ha.y, ha.z, ha.w, hb.x, hb.y, hb.z, hb.w};
                float a0 = 0.f, a1 = 0.f, a2 = 0.f, a3 = 0.f;
                #pragma unroll
                for (int k = 0; k < 8; k++) {
                    float h = hr[k];
                    float w0 = ph ? wB[0][k] : wF[0][k];
                    float w1 = ph ? wB[1][k] : wF[1][k];
                    float w2 = ph ? wB[2][k] : wF[2][k];
                    float w3 = ph ? wB[3][k] : wF[3][k];
                    a0 = fmaf(w0, h, a0);
                    a1 = fmaf(w1, h, a1);
                    a2 = fmaf(w2, h, a2);
                    a3 = fmaf(w3, h, a3);
                }
                int prow = og * 8 + hh * 4;
                part[prow + 0][hs] = a0;
                part[prow + 1][hs] = a1;
                part[prow + 2][hs] = a2;
                part[prow + 3][hs] = a3;
            }
            __syncthreads();   // S2

            // Phase 3: reduce 64 partials per output
            {
                float4 pv = *(const float4*)&part[row][sub << 2];
                float sv = (pv.x + pv.y) + (pv.z + pv.w);
                sv += __shfl_xor_sync(0xffffffffu, sv, 1);
                sv += __shfl_xor_sync(0xffffffffu, sv, 2);
                sv += __shfl_xor_sync(0xffffffffu, sv, 4);
                sv += __shfl_xor_sync(0xffffffffu, sv, 8);
                if (sub == 0) zbuf[row] = sv + (ph ? gcurB : gcurF);
            }
            __syncthreads();   // S3

            // Phase 4: gates (MUFU.TANH) + state update + coalesced PUBLISH
            if (tid < 8) {
                float zi = zbuf[0  + tid];
                float zf = zbuf[8  + tid];
                float zg = zbuf[16 + tid];
                float zo = zbuf[24 + tid];
                float ig = hsigmoid(zi);
                float fg = hsigmoid(zf);
                float gg = htanh(zg);
                float oo = hsigmoid(zo);
                float cst = ph ? cstB : cstF;
                cst = fmaf(fg, cst, ig * gg);
                float hv = oo * htanh(cst);
                if (ph) { cstB = cst; hvB = hv; } else { cstF = cst; hvF = hv; }

                int e = ebase + tid;
                st_rel(&g_hbuf[ph][p ^ 1][e],
                       ptag | (unsigned long long)__float_as_uint(hv));
            }
            __syncthreads();   // S4 — hold poll flood until publishes issued

            // Phase 5 (off critical path): output store + next gate prefetch
            if (tid < 8) {
                int e = ebase + tid;
                float hv  = ph ? hvB  : hvF;
                float cst = ph ? cstB : cstF;
                size_t orow = ph ? (size_t)(s ^ 7) : (size_t)s;
                out[orow * (2 * HID) + ph * HID + e] = hv;
                if (s == NSTEP - 1) {
                    out[(size_t)NSTEP * 2 * HID + ph * HID + e] = hv;
                    out[(size_t)NSTEP * 2 * HID + 2 * HID + ph * HID + e] = cst;
                }
            }
            if (sub == 0) {
                int ns = (s + 1 < NSTEP) ? (s + 1) : (NSTEP - 1);
                if (ph) gcurB = __ldg(g_gates + gqB + (size_t)ns * G4H);
                else    gcurF = __ldg(g_gates + gqF + (size_t)ns * G4H);
            }
        }
    }
}

// ---------------------------------------------------------------------------
extern "C" void kernel_launch(void* const* d_in, const int* in_sizes, int n_in,
                              void* d_out, int out_size)
{
    const float* x   = (const float*)d_in[0];
    const float* h0  = (const float*)d_in[1];
    const float* c0  = (const float*)d_in[2];
    const float* Wif = (const float*)d_in[3];
    const float* Whf = (const float*)d_in[4];
    const float* bf  = (const float*)d_in[5];
    const float* Wib = (const float*)d_in[6];
    const float* Whb = (const float*)d_in[7];
    const float* bb  = (const float*)d_in[8];
    float* out = (float*)d_out;

    dim3 ggrid(G4H / BN, NSTEP / BM, 2);
    gates_gemm<<<ggrid, 256>>>(x, Wif, bf, Wib, bb);
    lstm_scan<<<NCS, SCAN_THREADS>>>(h0, c0, Whf, Whb, out);
}

// round 17
// speedup vs baseline: 1.7566x; 1.7566x over previous
#include <cuda_runtime.h>
#include <cstdint>

// Problem constants
#define HID   512
#define NSTEP 8192          // BS*T = 1024*8
#define G4H   2048          // 4*HID
#define DIN   512

// Scan kernel config: CTAs 0..63 = forward, 64..127 = backward.
#define NC           128
#define SCAN_THREADS 512
#define HC           8      // hidden indices per CTA (single direction)

// GEMM config
#define BM 128
#define BN 128
#define BK 16

__device__ float g_gates[(size_t)2 * NSTEP * G4H];
__device__ __align__(128) unsigned long long g_hbuf[2][2][HID];  // [dir][parity][e]

// ---------------------------------------------------------------------------
__device__ __forceinline__ void st_rel(unsigned long long* p, unsigned long long v) {
    asm volatile("st.global.relaxed.gpu.u64 [%0], %1;" :: "l"(p), "l"(v) : "memory");
}
__device__ __forceinline__ void ld_rel_v2(const unsigned long long* p,
                                          unsigned long long& a, unsigned long long& b) {
    asm volatile("ld.relaxed.gpu.global.v2.u64 {%0, %1}, [%2];"
                 : "=l"(a), "=l"(b) : "l"(p) : "memory");
}
// Hardware tanh (MUFU.TANH): one op per transcendental.
__device__ __forceinline__ float htanh(float x) {
    float y;
    asm("tanh.approx.f32 %0, %1;" : "=f"(y) : "f"(x));
    return y;
}
__device__ __forceinline__ float hsigmoid(float x) {
    return fmaf(htanh(0.5f * x), 0.5f, 0.5f);
}

// ---------------------------------------------------------------------------
// Kernel 1: gates GEMM with register-staged double buffering.
// ---------------------------------------------------------------------------
__global__ __launch_bounds__(256) void gates_gemm(
    const float* __restrict__ x,
    const float* __restrict__ Wif, const float* __restrict__ bf,
    const float* __restrict__ Wib, const float* __restrict__ bb)
{
    const int dir = blockIdx.z;
    const float* __restrict__ W    = dir ? Wib : Wif;
    const float* __restrict__ bias = dir ? bb  : bf;
    float* __restrict__ out = g_gates + (size_t)dir * NSTEP * G4H;

    __shared__ __align__(16) float As[BK][BM + 4];
    __shared__ __align__(16) float Bs[BK][BN + 4];

    const int tid  = threadIdx.x;
    const int row0 = blockIdx.y * BM;
    const int col0 = blockIdx.x * BN;
    const int tx = tid & 15;
    const int ty = tid >> 4;

    // Staged-load addressing (two 512-thread slices per tile)
    const int m0 = tid >> 2,         kq0 = (tid & 3) * 4;
    const int m1 = (tid + 256) >> 2, kq1 = ((tid + 256) & 3) * 4;
    const int xr0 = dir ? ((row0 + m0) ^ 7) : (row0 + m0);
    const int xr1 = dir ? ((row0 + m1) ^ 7) : (row0 + m1);
    const float* xp0 = x + (size_t)xr0 * DIN + kq0;
    const float* xp1 = x + (size_t)xr1 * DIN + kq1;
    const float* wp0 = W + (size_t)(col0 + m0) * DIN + kq0;
    const float* wp1 = W + (size_t)(col0 + m1) * DIN + kq1;

    float acc[8][8];
    #pragma unroll
    for (int i = 0; i < 8; i++)
        #pragma unroll
        for (int j = 0; j < 8; j++) acc[i][j] = 0.f;

    // Prologue: stage k-tile 0 into registers
    float4 xv0 = *(const float4*)(xp0);
    float4 xv1 = *(const float4*)(xp1);
    float4 wv0 = *(const float4*)(wp0);
    float4 wv1 = *(const float4*)(wp1);

    for (int k0 = 0; k0 < DIN; k0 += BK) {
        // Commit staged tile to smem
        As[kq0 + 0][m0] = xv0.x; As[kq0 + 1][m0] = xv0.y;
        As[kq0 + 2][m0] = xv0.z; As[kq0 + 3][m0] = xv0.w;
        As[kq1 + 0][m1] = xv1.x; As[kq1 + 1][m1] = xv1.y;
        As[kq1 + 2][m1] = xv1.z; As[kq1 + 3][m1] = xv1.w;
        Bs[kq0 + 0][m0] = wv0.x; Bs[kq0 + 1][m0] = wv0.y;
        Bs[kq0 + 2][m0] = wv0.z; Bs[kq0 + 3][m0] = wv0.w;
        Bs[kq1 + 0][m1] = wv1.x; Bs[kq1 + 1][m1] = wv1.y;
        Bs[kq1 + 2][m1] = wv1.z; Bs[kq1 + 3][m1] = wv1.w;
        __syncthreads();

        // Prefetch next k-tile into registers (overlaps the FFMAs below)
        if (k0 + BK < DIN) {
            xv0 = *(const float4*)(xp0 + k0 + BK);
            xv1 = *(const float4*)(xp1 + k0 + BK);
            wv0 = *(const float4*)(wp0 + k0 + BK);
            wv1 = *(const float4*)(wp1 + k0 + BK);
        }

        #pragma unroll
        for (int kk = 0; kk < BK; kk++) {
            float a[8], b[8];
            float4 a0 = *(const float4*)&As[kk][ty * 8];
            float4 a1 = *(const float4*)&As[kk][ty * 8 + 4];
            a[0]=a0.x; a[1]=a0.y; a[2]=a0.z; a[3]=a0.w;
            a[4]=a1.x; a[5]=a1.y; a[6]=a1.z; a[7]=a1.w;
            float4 b0 = *(const float4*)&Bs[kk][tx * 8];
            float4 b1 = *(const float4*)&Bs[kk][tx * 8 + 4];
            b[0]=b0.x; b[1]=b0.y; b[2]=b0.z; b[3]=b0.w;
            b[4]=b1.x; b[5]=b1.y; b[6]=b1.z; b[7]=b1.w;
            #pragma unroll
            for (int i = 0; i < 8; i++)
                #pragma unroll
                for (int j = 0; j < 8; j++)
                    acc[i][j] = fmaf(a[i], b[j], acc[i][j]);
        }
        __syncthreads();
    }

    #pragma unroll
    for (int i = 0; i < 8; i++) {
        size_t srow = row0 + ty * 8 + i;
        #pragma unroll
        for (int j = 0; j < 8; j++) {
            int c = col0 + tx * 8 + j;
            out[srow * G4H + c] = acc[i][j] + bias[c];
        }
    }
}

// ---------------------------------------------------------------------------
// Kernel 2: direction-split persistent scan — byte-exact R11 (best: 9.46 ms).
// ---------------------------------------------------------------------------
__global__ void __launch_bounds__(SCAN_THREADS, 1) lstm_scan(
    const float* __restrict__ h0,
    const float* __restrict__ c0,
    const float* __restrict__ Whf,
    const float* __restrict__ Whb,
    float* __restrict__ out)
{
    const int cta   = blockIdx.x;
    const int tid   = threadIdx.x;
    const int dir   = cta >> 6;          // 0 fwd / 1 bwd
    const int ebase = (cta & 63) * HC;   // first owned hidden index

    __shared__ __align__(16) float sh[2][HID];      // own-dir hidden state
    __shared__ __align__(16) float part[32][64];    // [gate*8 + h'][slice]
    __shared__ float zbuf[32];

    // ---- matvec role: gate, h'-half, h-slice ----
    const int og = (tid >> 6) & 3;       // gate 0..3
    const int hh = tid >> 8;             // 0: h' 0..3, 1: h' 4..7
    const int hs = tid & 63;             // h slice [hs*8, hs*8+8)

    const float* __restrict__ Wd = dir ? Whb : Whf;
    float w[4][8];                       // 4 outputs (q) x 8 h-elems
    #pragma unroll
    for (int q = 0; q < 4; q++) {
        size_t row = (size_t)og * HID + ebase + hh * 4 + q;
        #pragma unroll
        for (int k = 0; k < 8; k++)
            w[q][k] = Wd[row * HID + hs * 8 + k];
    }

    // ---- reduce role ----
    const int row = tid >> 4;            // 0..31 = gate*8 + h'
    const int sub = tid & 15;
    const int rg  = row >> 3;            // gate
    const int rh  = row & 7;             // h'
    const size_t gq_base = (size_t)dir * NSTEP * G4H
                         + (size_t)rg * HID + ebase + rh;
    float gcur = 0.f;
    if (sub == 0) gcur = __ldg(g_gates + gq_base);

    // ---- update role (tid<8): owns h' = tid ----
    float cst = 0.f, hv = 0.f;
    if (tid < 8) {
        int e = ebase + tid;
        hv  = h0[dir * HID + e];
        cst = c0[dir * HID + e];
        unsigned long long pk =
            (((unsigned long long)1u) << 32) | (unsigned long long)__float_as_uint(hv);
        st_rel(&g_hbuf[dir][0][e], pk);
    }

    for (int s = 0; s < NSTEP; s++) {
        // Phase 1: threads 0..255 poll 2 slots each with one LDG.128
        if (tid < 256) {
            const unsigned want = (unsigned)(s + 1);
            const unsigned long long* bp = &g_hbuf[dir][s & 1][tid * 2];
            unsigned long long v0, v1;
            do {
                ld_rel_v2(bp, v0, v1);
            } while ((unsigned)(v0 >> 32) != want || (unsigned)(v1 >> 32) != want);
            float2 hvals = make_float2(__uint_as_float((unsigned)v0),
                                       __uint_as_float((unsigned)v1));
            *(float2*)&sh[s & 1][tid * 2] = hvals;
        }
        __syncthreads();   // S1

        // Phase 2: register-tiled matvec partials (plain FFMA)
        {
            float4 ha = *(const float4*)&sh[s & 1][hs * 8];
            float4 hb = *(const float4*)&sh[s & 1][hs * 8 + 4];
            float hr[8] = {ha.x, ha.y, ha.z, ha.w, hb.x, hb.y, hb.z, hb.w};
            float a0 = 0.f, a1 = 0.f, a2 = 0.f, a3 = 0.f;
            #pragma unroll
            for (int k = 0; k < 8; k++) {
                float h = hr[k];
                a0 = fmaf(w[0][k], h, a0);
                a1 = fmaf(w[1][k], h, a1);
                a2 = fmaf(w[2][k], h, a2);
                a3 = fmaf(w[3][k], h, a3);
            }
            int prow = og * 8 + hh * 4;
            part[prow + 0][hs] = a0;
            part[prow + 1][hs] = a1;
            part[prow + 2][hs] = a2;
            part[prow + 3][hs] = a3;
        }
        __syncthreads();   // S2

        // Phase 3: reduce 64 partials per output
        {
            float4 p = *(const float4*)&part[row][sub << 2];
            float sv = (p.x + p.y) + (p.z + p.w);
            sv += __shfl_xor_sync(0xffffffffu, sv, 1);
            sv += __shfl_xor_sync(0xffffffffu, sv, 2);
            sv += __shfl_xor_sync(0xffffffffu, sv, 4);
            sv += __shfl_xor_sync(0xffffffffu, sv, 8);
            if (sub == 0) zbuf[row] = sv + gcur;
        }
        __syncthreads();   // S3

        // Phase 4: gates (MUFU.TANH) + state update + PUBLISH
        if (tid < 8) {
            float zi = zbuf[0  + tid];
            float zf = zbuf[8  + tid];
            float zg = zbuf[16 + tid];
            float zo = zbuf[24 + tid];
            float ig = hsigmoid(zi);
            float fg = hsigmoid(zf);
            float gg = htanh(zg);
            float oo = hsigmoid(zo);
            cst = fmaf(fg, cst, ig * gg);
            hv  = oo * htanh(cst);

            int e = ebase + tid;
            unsigned long long pk =
                (((unsigned long long)(unsigned)(s + 2)) << 32) |
                (unsigned long long)__float_as_uint(hv);
            st_rel(&g_hbuf[dir][(s + 1) & 1][e], pk);
        }
        __syncthreads();   // S4 — hold poll flood until all publishes issued

        // Phase 5 (off critical path): output store + next gate prefetch
        if (tid < 8) {
            int e = ebase + tid;
            size_t orow = dir ? (size_t)(s ^ 7) : (size_t)s;
            out[orow * (2 * HID) + dir * HID + e] = hv;
            if (s == NSTEP - 1) {
                out[(size_t)NSTEP * 2 * HID + dir * HID + e] = hv;
                out[(size_t)NSTEP * 2 * HID + 2 * HID + dir * HID + e] = cst;
            }
        }
        if (sub == 0) {
            int ns = (s + 1 < NSTEP) ? (s + 1) : (NSTEP - 1);
            gcur = __ldg(g_gates + gq_base + (size_t)ns * G4H);
        }
    }
}

// ---------------------------------------------------------------------------
extern "C" void kernel_launch(void* const* d_in, const int* in_sizes, int n_in,
                              void* d_out, int out_size)
{
    const float* x   = (const float*)d_in[0];
    const float* h0  = (const float*)d_in[1];
    const float* c0  = (const float*)d_in[2];
    const float* Wif = (const float*)d_in[3];
    const float* Whf = (const float*)d_in[4];
    const float* bf  = (const float*)d_in[5];
    const float* Wib = (const float*)d_in[6];
    const float* Whb = (const float*)d_in[7];
    const float* bb  = (const float*)d_in[8];
    float* out = (float*)d_out;

    dim3 ggrid(G4H / BN, NSTEP / BM, 2);
    gates_gemm<<<ggrid, 256>>>(x, Wif, bf, Wib, bb);
    lstm_scan<<<NC, SCAN_THREADS>>>(h0, c0, Whf, Whb, out);
}